// round 7
// baseline (speedup 1.0000x reference)
#include <cuda_runtime.h>
#include <math.h>

#define NN    50000
#define FIN   512
#define HEADS 4
#define HID   64
#define NCLS  40
#define EE    800000
#define ETOT  (EE + NN)      // 850000 (with self loops)
#define D1    (HEADS * HID)  // 256

// ---------------- scratch (device globals; no allocation allowed) ----------
static __device__ float g_h  [(size_t)NN * D1];      // GEMM output h
static __device__ float g_buf[(size_t)NN * D1];      // aggregated output / next input
static __device__ float g_e  [(size_t)ETOT * HEADS]; // unnormalized alpha, CSR order
static __device__ float g_as [NN * HEADS];
static __device__ float g_ad [NN * HEADS];
static __device__ float g_r  [NN * HEADS];           // 1/denominator per node,head
static __device__ int   g_deg[NN];
static __device__ int   g_off[NN + 1];
static __device__ int   g_cur[NN];
static __device__ int   g_srcs[ETOT];                // src node ids grouped by dst

// ---------------- tf32 helpers ---------------------------------------------
__device__ __forceinline__ unsigned f2tf(float f) {
    unsigned u;
    asm("cvt.rna.tf32.f32 %0, %1;" : "=r"(u) : "f"(f));
    return u;
}
__device__ __forceinline__ uint2 split2(float f) {
    unsigned hi = f2tf(f);
    float r = f - __uint_as_float(hi);
    return make_uint2(hi, f2tf(r));
}
__device__ __forceinline__ void mma_tf32(float c[4],
                                         unsigned a0, unsigned a1, unsigned a2, unsigned a3,
                                         unsigned b0, unsigned b1) {
    asm volatile(
        "mma.sync.aligned.m16n8k8.row.col.f32.tf32.tf32.f32 "
        "{%0,%1,%2,%3}, {%4,%5,%6,%7}, {%8,%9}, {%0,%1,%2,%3};"
        : "+f"(c[0]), "+f"(c[1]), "+f"(c[2]), "+f"(c[3])
        : "r"(a0), "r"(a1), "r"(a2), "r"(a3), "r"(b0), "r"(b1));
}

__device__ __forceinline__ void cp16(unsigned dst, const void* src, int srcsize) {
    asm volatile("cp.async.cg.shared.global [%0], [%1], 16, %2;"
                 :: "r"(dst), "l"(src), "r"(srcsize));
}

// ---------------- GEMM: C[M,N] = A[M,K] @ W[K,N], 3xTF32 tensor cores ------
// 128x128 block tile, BK=16, 8 warps (2m x 4n), warp tile 64x32.
// cp.async 2-stage double buffer (raw tiles) + cooperative one-time tf32
// hi/lo split into packed uint2 smem; consume loop is pure LDS.64 + MMA.
#define BK   16
#define RAK  20    // raw A k-stride (floats)
#define S2   132   // split-buffer stride (uint2)
// dynamic smem layout (floats):
//   rA : 2 * 128 * RAK          = 5120
//   rB : 2 * BK * 128           = 4096
//   As2: BK * S2 uint2          = 4224 floats
//   Bs2: BK * S2 uint2          = 4224 floats
#define SM_RA   0
#define SM_RB   (2 * 128 * RAK)
#define SM_AS2  (SM_RB + 2 * BK * 128)
#define SM_BS2  (SM_AS2 + BK * S2 * 2)
#define SM_TOTF (SM_BS2 + BK * S2 * 2)          // total floats
#define GEMM_SMEM_BYTES (SM_TOTF * 4)           // 70656

__global__ void __launch_bounds__(256, 2) gemm_tf32(const float* __restrict__ A,
                                                    const float* __restrict__ W,
                                                    float* __restrict__ C,
                                                    int M, int N, int K) {
    extern __shared__ float sm[];
    float* rA  = sm + SM_RA;               // [2][128][RAK]
    float* rB  = sm + SM_RB;               // [2][BK][128]
    uint2* As2 = (uint2*)(sm + SM_AS2);    // [BK][S2]  (k, m)
    uint2* Bs2 = (uint2*)(sm + SM_BS2);    // [BK][S2]  (k, n)

    int tid  = threadIdx.x;
    int lane = tid & 31;
    int wid  = tid >> 5;
    int warpM = wid & 1;
    int warpN = wid >> 1;
    int g = lane >> 2, t = lane & 3;

    int bm = blockIdx.x * 128;
    int bn = blockIdx.y * 128;

    float acc[4][4][4];
#pragma unroll
    for (int i = 0; i < 4; i++)
#pragma unroll
        for (int j = 0; j < 4; j++)
#pragma unroll
            for (int q = 0; q < 4; q++) acc[i][j][q] = 0.f;

    // cp.async loader mapping
    int ar = tid >> 1;             // 0..127 : A row within tile
    int ak = (tid & 1) * 8;        // 0/8    : A k base
    int bkr = tid >> 4;            // 0..15  : B k row
    int bc  = (tid & 15) * 8;      // 0..120 : B col base
    int arow = bm + ar; if (arow >= M) arow = M - 1;   // clamp (extra rows unused)
    int bs0 = (bn + bc + 3 < N) ? 16 : 0;              // zero-fill OOB columns
    int bs1 = (bn + bc + 7 < N) ? 16 : 0;
    const float* aptr = A + (size_t)arow * K + ak;
    const float* bptr = W + (size_t)bkr * N + bn + bc;

    unsigned dA = (unsigned)__cvta_generic_to_shared(rA) + (ar * RAK + ak) * 4;
    unsigned dB = (unsigned)__cvta_generic_to_shared(rB) + (bkr * 128 + bc) * 4;
    const unsigned stA = 128 * RAK * 4;
    const unsigned stB = BK * 128 * 4;

    // split-pass mapping: 256 threads x 16 elements (8 A + 8 B)
    int sm_i = tid & 127;          // A row / B col
    int sk8  = (tid >> 7) * 8;     // k base 0 or 8

    int T = K / BK;
    // prologue: tile 0 -> stage 0
    cp16(dA,      aptr,     16);
    cp16(dA + 16, aptr + 4, 16);
    cp16(dB,      bptr,     bs0);
    cp16(dB + 16, bptr + 4, bs1);
    asm volatile("cp.async.commit_group;");

    int rowb = warpM * 64 + g;
    int colb = warpN * 32 + g;

    for (int tt = 0; tt < T; tt++) {
        int cur = tt & 1;
        if (tt + 1 < T) {
            int nxt = cur ^ 1;
            const float* ap = aptr + (tt + 1) * BK;
            const float* bp = bptr + (size_t)(tt + 1) * BK * N;
            cp16(dA + nxt * stA,      ap,     16);
            cp16(dA + nxt * stA + 16, ap + 4, 16);
            cp16(dB + nxt * stB,      bp,     bs0);
            cp16(dB + nxt * stB + 16, bp + 4, bs1);
            asm volatile("cp.async.commit_group;");
            asm volatile("cp.async.wait_group 1;");
        } else {
            asm volatile("cp.async.commit_group;");
            asm volatile("cp.async.wait_group 0;");
        }
        __syncthreads();   // raw[cur] ready; prev consume done (split bufs free)

        // cooperative split: raw -> packed uint2 (each element split once)
        {
            const float* ra = rA + cur * (128 * RAK) + sm_i * RAK + sk8;
            float4 v0 = *(const float4*)ra;
            float4 v1 = *(const float4*)(ra + 4);
            As2[(sk8 + 0) * S2 + sm_i] = split2(v0.x);
            As2[(sk8 + 1) * S2 + sm_i] = split2(v0.y);
            As2[(sk8 + 2) * S2 + sm_i] = split2(v0.z);
            As2[(sk8 + 3) * S2 + sm_i] = split2(v0.w);
            As2[(sk8 + 4) * S2 + sm_i] = split2(v1.x);
            As2[(sk8 + 5) * S2 + sm_i] = split2(v1.y);
            As2[(sk8 + 6) * S2 + sm_i] = split2(v1.z);
            As2[(sk8 + 7) * S2 + sm_i] = split2(v1.w);
            const float* rb = rB + cur * (BK * 128) + sk8 * 128 + sm_i;
#pragma unroll
            for (int j = 0; j < 8; j++)
                Bs2[(sk8 + j) * S2 + sm_i] = split2(rb[j * 128]);
        }
        __syncthreads();   // split buffers ready

#pragma unroll
        for (int kk = 0; kk < BK; kk += 8) {
            uint2 aF[4][4], bF[4][2];
#pragma unroll
            for (int mt = 0; mt < 4; mt++) {
                int r = rowb + mt * 16;
                aF[mt][0] = As2[(kk + t    ) * S2 + r    ];
                aF[mt][1] = As2[(kk + t    ) * S2 + r + 8];
                aF[mt][2] = As2[(kk + t + 4) * S2 + r    ];
                aF[mt][3] = As2[(kk + t + 4) * S2 + r + 8];
            }
#pragma unroll
            for (int nt = 0; nt < 4; nt++) {
                int c = colb + nt * 8;
                bF[nt][0] = Bs2[(kk + t    ) * S2 + c];
                bF[nt][1] = Bs2[(kk + t + 4) * S2 + c];
            }
#pragma unroll
            for (int mt = 0; mt < 4; mt++)
#pragma unroll
                for (int nt = 0; nt < 4; nt++) {
                    mma_tf32(acc[mt][nt],
                             aF[mt][0].x, aF[mt][1].x, aF[mt][2].x, aF[mt][3].x,
                             bF[nt][0].y, bF[nt][1].y);
                    mma_tf32(acc[mt][nt],
                             aF[mt][0].y, aF[mt][1].y, aF[mt][2].y, aF[mt][3].y,
                             bF[nt][0].x, bF[nt][1].x);
                    mma_tf32(acc[mt][nt],
                             aF[mt][0].x, aF[mt][1].x, aF[mt][2].x, aF[mt][3].x,
                             bF[nt][0].x, bF[nt][1].x);
                }
        }
        // next-iteration top __syncthreads() protects split buffers
    }

    // store C
#pragma unroll
    for (int mt = 0; mt < 4; mt++) {
        int row0 = bm + warpM * 64 + mt * 16 + g;
#pragma unroll
        for (int nt = 0; nt < 4; nt++) {
            int col = bn + warpN * 32 + nt * 8 + 2 * t;
            if (col < N) {
                if (row0 < M)
                    *(float2*)&C[(size_t)row0 * N + col] =
                        make_float2(acc[mt][nt][0], acc[mt][nt][1]);
                if (row0 + 8 < M)
                    *(float2*)&C[(size_t)(row0 + 8) * N + col] =
                        make_float2(acc[mt][nt][2], acc[mt][nt][3]);
            }
        }
    }
}

// ---------------- CSR build --------------------------------------------------
__global__ void k_zero_deg() {
    int i = blockIdx.x * blockDim.x + threadIdx.x;
    if (i < NN) g_deg[i] = 0;
}

__global__ void k_count(const int* __restrict__ ei) {
    int e = blockIdx.x * blockDim.x + threadIdx.x;
    if (e >= ETOT) return;
    int d = e < EE ? ei[EE + e] : e - EE;
    atomicAdd(&g_deg[d], 1);
}

__global__ __launch_bounds__(1024) void k_scan() {
    __shared__ int part[1024];
    const int SEG = (NN + 1023) / 1024;
    int t = threadIdx.x;
    int lo = t * SEG, hi = min(NN, lo + SEG);
    int s = 0;
    for (int i = lo; i < hi; i++) s += g_deg[i];
    part[t] = s;
    __syncthreads();
    for (int off = 1; off < 1024; off <<= 1) {
        int v = 0;
        if (t >= off) v = part[t - off];
        __syncthreads();
        if (t >= off) part[t] += v;
        __syncthreads();
    }
    int run = t ? part[t - 1] : 0;
    for (int i = lo; i < hi; i++) {
        g_off[i] = run;
        g_cur[i] = run;
        run += g_deg[i];
    }
    if (t == 0) g_off[NN] = part[1023];
}

__global__ void k_scatter(const int* __restrict__ ei) {
    int e = blockIdx.x * blockDim.x + threadIdx.x;
    if (e >= ETOT) return;
    int s, d;
    if (e < EE) { s = ei[e]; d = ei[EE + e]; }
    else        { s = d = e - EE; }
    int pos = atomicAdd(&g_cur[d], 1);
    g_srcs[pos] = s;
}

// ---------------- per-node: a_s, a_d -----------------------------------------
__global__ void node_prep(const float* __restrict__ h,
                          const float* __restrict__ atts,
                          const float* __restrict__ attd,
                          int H, int C) {
    int warp = (blockIdx.x * blockDim.x + threadIdx.x) >> 5;
    int lane = threadIdx.x & 31;
    if (warp >= NN) return;
    int HC = H * C;
    const float* hr = h + (size_t)warp * HC;
    for (int hd = 0; hd < H; hd++) {
        float s = 0.f, d = 0.f;
        for (int c = lane; c < C; c += 32) {
            float v = hr[hd * C + c];
            s += v * atts[hd * C + c];
            d += v * attd[hd * C + c];
        }
#pragma unroll
        for (int o = 16; o; o >>= 1) {
            s += __shfl_down_sync(0xFFFFFFFFu, s, o);
            d += __shfl_down_sync(0xFFFFFFFFu, d, o);
        }
        if (lane == 0) {
            g_as[warp * H + hd] = s;
            g_ad[warp * H + hd] = d;
        }
    }
}

// ---------------- softmax coefs (H=4): one warp per dst node -----------------
__global__ __launch_bounds__(256) void attn_coef4() {
    int node = (blockIdx.x * blockDim.x + threadIdx.x) >> 5;
    int lane = threadIdx.x & 31;
    if (node >= NN) return;
    int beg = g_off[node];
    int deg = g_off[node + 1] - beg;

    float4 adv = *(const float4*)&g_ad[node * 4];
    float mx0 = -1e30f, mx1 = -1e30f, mx2 = -1e30f, mx3 = -1e30f;

    float c0 = 0.f, c1 = 0.f, c2 = 0.f, c3 = 0.f;
    bool have = lane < deg;
    if (have) {
        int s = g_srcs[beg + lane];
        float4 av = *(const float4*)&g_as[s * 4];
        c0 = av.x + adv.x; c1 = av.y + adv.y;
        c2 = av.z + adv.z; c3 = av.w + adv.w;
        c0 = c0 > 0.f ? c0 : 0.2f * c0;
        c1 = c1 > 0.f ? c1 : 0.2f * c1;
        c2 = c2 > 0.f ? c2 : 0.2f * c2;
        c3 = c3 > 0.f ? c3 : 0.2f * c3;
        mx0 = c0; mx1 = c1; mx2 = c2; mx3 = c3;
    }
    for (int base = 32; base < deg; base += 32) {
        int i = base + lane;
        if (i < deg) {
            int s = g_srcs[beg + i];
            float4 av = *(const float4*)&g_as[s * 4];
            float v0 = av.x + adv.x, v1 = av.y + adv.y;
            float v2 = av.z + adv.z, v3 = av.w + adv.w;
            v0 = v0 > 0.f ? v0 : 0.2f * v0;
            v1 = v1 > 0.f ? v1 : 0.2f * v1;
            v2 = v2 > 0.f ? v2 : 0.2f * v2;
            v3 = v3 > 0.f ? v3 : 0.2f * v3;
            mx0 = fmaxf(mx0, v0); mx1 = fmaxf(mx1, v1);
            mx2 = fmaxf(mx2, v2); mx3 = fmaxf(mx3, v3);
        }
    }
#pragma unroll
    for (int o = 16; o; o >>= 1) {
        mx0 = fmaxf(mx0, __shfl_xor_sync(0xFFFFFFFFu, mx0, o));
        mx1 = fmaxf(mx1, __shfl_xor_sync(0xFFFFFFFFu, mx1, o));
        mx2 = fmaxf(mx2, __shfl_xor_sync(0xFFFFFFFFu, mx2, o));
        mx3 = fmaxf(mx3, __shfl_xor_sync(0xFFFFFFFFu, mx3, o));
    }
    float s0 = 0.f, s1 = 0.f, s2 = 0.f, s3 = 0.f;
    if (have) {
        float a0 = __expf(c0 - mx0), a1 = __expf(c1 - mx1);
        float a2 = __expf(c2 - mx2), a3 = __expf(c3 - mx3);
        *(float4*)&g_e[(size_t)(beg + lane) * 4] = make_float4(a0, a1, a2, a3);
        s0 = a0; s1 = a1; s2 = a2; s3 = a3;
    }
    for (int base = 32; base < deg; base += 32) {
        int i = base + lane;
        if (i < deg) {
            int s = g_srcs[beg + i];
            float4 av = *(const float4*)&g_as[s * 4];
            float v0 = av.x + adv.x, v1 = av.y + adv.y;
            float v2 = av.z + adv.z, v3 = av.w + adv.w;
            v0 = v0 > 0.f ? v0 : 0.2f * v0;
            v1 = v1 > 0.f ? v1 : 0.2f * v1;
            v2 = v2 > 0.f ? v2 : 0.2f * v2;
            v3 = v3 > 0.f ? v3 : 0.2f * v3;
            float a0 = __expf(v0 - mx0), a1 = __expf(v1 - mx1);
            float a2 = __expf(v2 - mx2), a3 = __expf(v3 - mx3);
            *(float4*)&g_e[(size_t)(beg + i) * 4] = make_float4(a0, a1, a2, a3);
            s0 += a0; s1 += a1; s2 += a2; s3 += a3;
        }
    }
#pragma unroll
    for (int o = 16; o; o >>= 1) {
        s0 += __shfl_xor_sync(0xFFFFFFFFu, s0, o);
        s1 += __shfl_xor_sync(0xFFFFFFFFu, s1, o);
        s2 += __shfl_xor_sync(0xFFFFFFFFu, s2, o);
        s3 += __shfl_xor_sync(0xFFFFFFFFu, s3, o);
    }
    if (lane == 0)
        *(float4*)&g_r[node * 4] = make_float4(1.f / s0, 1.f / s1, 1.f / s2, 1.f / s3);
}

// ---------------- softmax coefs (H=1) ----------------------------------------
__global__ __launch_bounds__(256) void attn_coef1() {
    int node = (blockIdx.x * blockDim.x + threadIdx.x) >> 5;
    int lane = threadIdx.x & 31;
    if (node >= NN) return;
    int beg = g_off[node];
    int deg = g_off[node + 1] - beg;

    float adv = g_ad[node];
    float vc = 0.f;
    bool have = lane < deg;
    float mx = -1e30f;
    if (have) {
        int s = g_srcs[beg + lane];
        float v = g_as[s] + adv;
        vc = v > 0.f ? v : 0.2f * v;
        mx = vc;
    }
    for (int base = 32; base < deg; base += 32) {
        int i = base + lane;
        if (i < deg) {
            int s = g_srcs[beg + i];
            float v = g_as[s] + adv;
            v = v > 0.f ? v : 0.2f * v;
            mx = fmaxf(mx, v);
        }
    }
#pragma unroll
    for (int o = 16; o; o >>= 1) mx = fmaxf(mx, __shfl_xor_sync(0xFFFFFFFFu, mx, o));
    float sm = 0.f;
    if (have) {
        float a = __expf(vc - mx);
        g_e[beg + lane] = a;
        sm = a;
    }
    for (int base = 32; base < deg; base += 32) {
        int i = base + lane;
        if (i < deg) {
            int s = g_srcs[beg + i];
            float v = g_as[s] + adv;
            v = v > 0.f ? v : 0.2f * v;
            float a = __expf(v - mx);
            g_e[beg + i] = a;
            sm += a;
        }
    }
#pragma unroll
    for (int o = 16; o; o >>= 1) sm += __shfl_xor_sync(0xFFFFFFFFu, sm, o);
    if (lane == 0) g_r[node] = 1.f / sm;
}

// ---------------- aggregation: one warp per dst node, 256 channels ----------
__global__ __launch_bounds__(256) void aggr256(const float* __restrict__ h,
                                               const float* __restrict__ bias,
                                               float* __restrict__ obuf,
                                               int apply_elu) {
    int node = (blockIdx.x * blockDim.x + threadIdx.x) >> 5;
    int lane = threadIdx.x & 31;
    if (node >= NN) return;
    int beg = g_off[node];
    int deg = g_off[node + 1] - beg;
    int c  = lane * 8;
    int hd = lane >> 3;

    float4 a0 = make_float4(0.f, 0.f, 0.f, 0.f);
    float4 a1 = make_float4(0.f, 0.f, 0.f, 0.f);

    int sp = g_srcs[beg];                    // prefetch (deg >= 1 always)
    for (int i = 0; i < deg; i++) {
        int cs = sp;
        if (i + 1 < deg) sp = g_srcs[beg + i + 1];
        float4 cf = *(const float4*)&g_e[(size_t)(beg + i) * 4];
        float coef = hd == 0 ? cf.x : hd == 1 ? cf.y : hd == 2 ? cf.z : cf.w;
        const float4* hp = (const float4*)(h + (size_t)cs * 256 + c);
        float4 v0 = hp[0], v1 = hp[1];
        a0.x += coef * v0.x; a0.y += coef * v0.y;
        a0.z += coef * v0.z; a0.w += coef * v0.w;
        a1.x += coef * v1.x; a1.y += coef * v1.y;
        a1.z += coef * v1.z; a1.w += coef * v1.w;
    }
    float4 rv = *(const float4*)&g_r[node * 4];
    float r = hd == 0 ? rv.x : hd == 1 ? rv.y : hd == 2 ? rv.z : rv.w;
    float4 b0 = *(const float4*)&bias[c];
    float4 b1 = *(const float4*)&bias[c + 4];
    a0.x = a0.x * r + b0.x; a0.y = a0.y * r + b0.y;
    a0.z = a0.z * r + b0.z; a0.w = a0.w * r + b0.w;
    a1.x = a1.x * r + b1.x; a1.y = a1.y * r + b1.y;
    a1.z = a1.z * r + b1.z; a1.w = a1.w * r + b1.w;
    if (apply_elu) {
        a0.x = a0.x > 0.f ? a0.x : expm1f(a0.x);
        a0.y = a0.y > 0.f ? a0.y : expm1f(a0.y);
        a0.z = a0.z > 0.f ? a0.z : expm1f(a0.z);
        a0.w = a0.w > 0.f ? a0.w : expm1f(a0.w);
        a1.x = a1.x > 0.f ? a1.x : expm1f(a1.x);
        a1.y = a1.y > 0.f ? a1.y : expm1f(a1.y);
        a1.z = a1.z > 0.f ? a1.z : expm1f(a1.z);
        a1.w = a1.w > 0.f ? a1.w : expm1f(a1.w);
    }
    float4* op = (float4*)(obuf + (size_t)node * 256 + c);
    op[0] = a0;
    op[1] = a1;
}

// ---------------- aggregation, layer 3: 40 channels, H=1 ---------------------
__global__ __launch_bounds__(256) void aggr40(const float* __restrict__ h,
                                              const float* __restrict__ bias,
                                              float* __restrict__ out) {
    int node = (blockIdx.x * blockDim.x + threadIdx.x) >> 5;
    int lane = threadIdx.x & 31;
    if (node >= NN) return;
    int beg = g_off[node];
    int deg = g_off[node + 1] - beg;

    float4 acc = make_float4(0.f, 0.f, 0.f, 0.f);
    int c = lane * 4;
    bool act = lane < 10;

    int sp = g_srcs[beg];
    for (int i = 0; i < deg; i++) {
        int cs = sp;
        if (i + 1 < deg) sp = g_srcs[beg + i + 1];
        float coef = g_e[beg + i];
        if (act) {
            float4 v = *(const float4*)(h + (size_t)cs * 40 + c);
            acc.x += coef * v.x; acc.y += coef * v.y;
            acc.z += coef * v.z; acc.w += coef * v.w;
        }
    }
    if (act) {
        float r = g_r[node];
        float4 b = *(const float4*)&bias[c];
        acc.x = acc.x * r + b.x; acc.y = acc.y * r + b.y;
        acc.z = acc.z * r + b.z; acc.w = acc.w * r + b.w;
        *(float4*)(out + (size_t)node * 40 + c) = acc;
    }
}

// ---------------- driver ----------------------------------------------------
extern "C" void kernel_launch(void* const* d_in, const int* in_sizes, int n_in,
                              void* d_out, int out_size) {
    const float* x   = (const float*)d_in[0];
    const int*   ei  = (const int*)  d_in[1];
    const float* W1  = (const float*)d_in[2];
    const float* as1 = (const float*)d_in[3];
    const float* ad1 = (const float*)d_in[4];
    const float* b1  = (const float*)d_in[5];
    const float* W2  = (const float*)d_in[6];
    const float* as2 = (const float*)d_in[7];
    const float* ad2 = (const float*)d_in[8];
    const float* b2  = (const float*)d_in[9];
    const float* W3  = (const float*)d_in[10];
    const float* as3 = (const float*)d_in[11];
    const float* ad3 = (const float*)d_in[12];
    const float* b3  = (const float*)d_in[13];
    float* out = (float*)d_out;

    float *h, *buf;
    cudaGetSymbolAddress((void**)&h,   g_h);
    cudaGetSymbolAddress((void**)&buf, g_buf);

    cudaFuncSetAttribute(gemm_tf32, cudaFuncAttributeMaxDynamicSharedMemorySize,
                         GEMM_SMEM_BYTES);

    const int TB = 256;
    int gE = (ETOT + TB - 1) / TB;
    int gW = (NN * 32 + TB - 1) / TB;   // one warp per node

    // ---- CSR by dst (edge structure shared by all layers) ----
    k_zero_deg<<<(NN + TB - 1) / TB, TB>>>();
    k_count  <<<gE, TB>>>(ei);
    k_scan   <<<1, 1024>>>();
    k_scatter<<<gE, TB>>>(ei);

    // ---- layer 1 ----
    dim3 g1((NN + 127) / 128, (D1 + 127) / 128);
    gemm_tf32 <<<g1, TB, GEMM_SMEM_BYTES>>>(x, W1, h, NN, D1, FIN);
    node_prep <<<gW, TB>>>(h, as1, ad1, HEADS, HID);
    attn_coef4<<<gW, TB>>>();
    aggr256   <<<gW, TB>>>(h, b1, buf, 1);

    // ---- layer 2 ----
    gemm_tf32 <<<g1, TB, GEMM_SMEM_BYTES>>>(buf, W2, h, NN, D1, D1);
    node_prep <<<gW, TB>>>(h, as2, ad2, HEADS, HID);
    attn_coef4<<<gW, TB>>>();
    aggr256   <<<gW, TB>>>(h, b2, buf, 1);

    // ---- layer 3 ----
    dim3 g3((NN + 127) / 128, 1);
    gemm_tf32 <<<g3, TB, GEMM_SMEM_BYTES>>>(buf, W3, h, NN, NCLS, D1);
    node_prep <<<gW, TB>>>(h, as3, ad3, 1, NCLS);
    attn_coef1<<<gW, TB>>>();
    aggr40    <<<gW, TB>>>(h, b3, out);
}

// round 8
// speedup vs baseline: 1.0756x; 1.0756x over previous
#include <cuda_runtime.h>
#include <math.h>

#define NN    50000
#define FIN   512
#define HEADS 4
#define HID   64
#define NCLS  40
#define EE    800000
#define ETOT  (EE + NN)      // 850000 (with self loops)
#define D1    (HEADS * HID)  // 256

// ---------------- scratch (device globals; no allocation allowed) ----------
static __device__ float g_h  [(size_t)NN * D1];      // GEMM output h
static __device__ float g_buf[(size_t)NN * D1];      // aggregated output / next input
static __device__ float g_e  [(size_t)ETOT * HEADS]; // unnormalized alpha, CSR order
static __device__ float g_as [NN * HEADS];
static __device__ float g_ad [NN * HEADS];
static __device__ float g_r  [NN * HEADS];           // 1/denominator per node,head
static __device__ int   g_deg[NN];
static __device__ int   g_off[NN + 1];
static __device__ int   g_cur[NN];
static __device__ int   g_srcs[ETOT];                // src node ids grouped by dst

// ---------------- tf32 helpers ---------------------------------------------
__device__ __forceinline__ unsigned f2tf(float f) {
    unsigned u;
    asm("cvt.rna.tf32.f32 %0, %1;" : "=r"(u) : "f"(f));
    return u;
}
__device__ __forceinline__ void tf_split(float f, unsigned& hi, unsigned& lo) {
    hi = f2tf(f);
    float r = f - __uint_as_float(hi);
    lo = f2tf(r);
}
__device__ __forceinline__ void mma_tf32(float c[4],
                                         unsigned a0, unsigned a1, unsigned a2, unsigned a3,
                                         unsigned b0, unsigned b1) {
    asm volatile(
        "mma.sync.aligned.m16n8k8.row.col.f32.tf32.tf32.f32 "
        "{%0,%1,%2,%3}, {%4,%5,%6,%7}, {%8,%9}, {%0,%1,%2,%3};"
        : "+f"(c[0]), "+f"(c[1]), "+f"(c[2]), "+f"(c[3])
        : "r"(a0), "r"(a1), "r"(a2), "r"(a3), "r"(b0), "r"(b1));
}

__device__ __forceinline__ void cp16(unsigned dst, const void* src, int srcsize) {
    asm volatile("cp.async.cg.shared.global [%0], [%1], 16, %2;"
                 :: "r"(dst), "l"(src), "r"(srcsize));
}

// ---------------- GEMM: C[M,N] = A[M,K] @ W[K,N], 3xTF32 tensor cores ------
// 128x128 block tile, BK=16, 8 warps (2m x 4n), warp tile 64x32.
// cp.async 2-stage double buffer; in-loop tf32 split (R6 structure, proven).
// Fused epilogue: a_s/a_d per-row dots computed from accumulators and
// atomically accumulated into g_as/g_ad (replaces the node_prep kernel).
#define BK  16
#define SAK 20    // A smem k-stride (16 + 4 pad)
#define SB  136   // B smem n-stride
__global__ __launch_bounds__(256) void gemm_tf32(const float* __restrict__ A,
                                                 const float* __restrict__ W,
                                                 float* __restrict__ C,
                                                 int M, int N, int K,
                                                 const float* __restrict__ atts,
                                                 const float* __restrict__ attd,
                                                 int H, int Ch) {
    __shared__ __align__(16) float As[2][128][SAK];
    __shared__ __align__(16) float Bs[2][BK][SB];

    int tid  = threadIdx.x;
    int lane = tid & 31;
    int wid  = tid >> 5;
    int warpM = wid & 1;
    int warpN = wid >> 1;
    int g = lane >> 2, t = lane & 3;

    int bm = blockIdx.x * 128;
    int bn = blockIdx.y * 128;

    float acc[4][4][4];
#pragma unroll
    for (int i = 0; i < 4; i++)
#pragma unroll
        for (int j = 0; j < 4; j++)
#pragma unroll
            for (int q = 0; q < 4; q++) acc[i][j][q] = 0.f;

    // loader mapping
    int ar = tid >> 1;             // 0..127 : A row within tile
    int ak = (tid & 1) * 8;        // 0/8    : A k base
    int bkr = tid >> 4;            // 0..15  : B k row
    int bc  = (tid & 15) * 8;      // 0..120 : B col base
    int arow = bm + ar; if (arow >= M) arow = M - 1;   // clamp (rows >= M unused)
    int bs0 = (bn + bc + 3 < N) ? 16 : 0;              // zero-fill OOB columns
    int bs1 = (bn + bc + 7 < N) ? 16 : 0;
    const float* aptr = A + (size_t)arow * K + ak;
    const float* bptr = W + (size_t)bkr * N + bn + bc;

    unsigned sA = (unsigned)__cvta_generic_to_shared(&As[0][0][0]);
    unsigned sB = (unsigned)__cvta_generic_to_shared(&Bs[0][0][0]);
    unsigned dA = sA + (ar * SAK + ak) * 4;
    unsigned dB = sB + (bkr * SB + bc) * 4;
    const unsigned stA = 128 * SAK * 4;   // stage stride (bytes)
    const unsigned stB = BK * SB * 4;

    int T = K / BK;
    // prologue: tile 0 -> stage 0
    cp16(dA,      aptr,     16);
    cp16(dA + 16, aptr + 4, 16);
    cp16(dB,      bptr,     bs0);
    cp16(dB + 16, bptr + 4, bs1);
    asm volatile("cp.async.commit_group;");

    int rowb = warpM * 64 + g;
    int colb = warpN * 32 + g;

    for (int tt = 0; tt < T; tt++) {
        int cur = tt & 1;
        if (tt + 1 < T) {
            int nxt = cur ^ 1;
            const float* ap = aptr + (tt + 1) * BK;
            const float* bp = bptr + (size_t)(tt + 1) * BK * N;
            cp16(dA + nxt * stA,      ap,     16);
            cp16(dA + nxt * stA + 16, ap + 4, 16);
            cp16(dB + nxt * stB,      bp,     bs0);
            cp16(dB + nxt * stB + 16, bp + 4, bs1);
            asm volatile("cp.async.commit_group;");
            asm volatile("cp.async.wait_group 1;");
        } else {
            asm volatile("cp.async.commit_group;");
            asm volatile("cp.async.wait_group 0;");
        }
        __syncthreads();

        const float* Af = &As[cur][0][0];
        const float* Bf = &Bs[cur][0][0];
#pragma unroll
        for (int kk = 0; kk < BK; kk += 8) {
            unsigned aHi[4][4], aLo[4][4], bHi[4][2], bLo[4][2];
#pragma unroll
            for (int mt = 0; mt < 4; mt++) {
                int r = rowb + mt * 16;
                tf_split(Af[(r    ) * SAK + kk + t    ], aHi[mt][0], aLo[mt][0]);
                tf_split(Af[(r + 8) * SAK + kk + t    ], aHi[mt][1], aLo[mt][1]);
                tf_split(Af[(r    ) * SAK + kk + t + 4], aHi[mt][2], aLo[mt][2]);
                tf_split(Af[(r + 8) * SAK + kk + t + 4], aHi[mt][3], aLo[mt][3]);
            }
#pragma unroll
            for (int nt = 0; nt < 4; nt++) {
                int c = colb + nt * 8;
                tf_split(Bf[(kk + t    ) * SB + c], bHi[nt][0], bLo[nt][0]);
                tf_split(Bf[(kk + t + 4) * SB + c], bHi[nt][1], bLo[nt][1]);
            }
#pragma unroll
            for (int mt = 0; mt < 4; mt++)
#pragma unroll
                for (int nt = 0; nt < 4; nt++) {
                    mma_tf32(acc[mt][nt], aHi[mt][0], aHi[mt][1], aHi[mt][2], aHi[mt][3],
                             bLo[nt][0], bLo[nt][1]);
                    mma_tf32(acc[mt][nt], aLo[mt][0], aLo[mt][1], aLo[mt][2], aLo[mt][3],
                             bHi[nt][0], bHi[nt][1]);
                    mma_tf32(acc[mt][nt], aHi[mt][0], aHi[mt][1], aHi[mt][2], aHi[mt][3],
                             bHi[nt][0], bHi[nt][1]);
                }
        }
        __syncthreads();
    }

    // store C
#pragma unroll
    for (int mt = 0; mt < 4; mt++) {
        int row0 = bm + warpM * 64 + mt * 16 + g;
#pragma unroll
        for (int nt = 0; nt < 4; nt++) {
            int col = bn + warpN * 32 + nt * 8 + 2 * t;
            if (col < N) {
                if (row0 < M)
                    *(float2*)&C[(size_t)row0 * N + col] =
                        make_float2(acc[mt][nt][0], acc[mt][nt][1]);
                if (row0 + 8 < M)
                    *(float2*)&C[(size_t)(row0 + 8) * N + col] =
                        make_float2(acc[mt][nt][2], acc[mt][nt][3]);
            }
        }
    }

    // fused a_s/a_d epilogue: each warp's 32 cols lie within one head
    int colw = bn + warpN * 32;
    if (colw < N) {
        int hd = colw / Ch;
        float asv[4][2], adv[4][2];
#pragma unroll
        for (int nt = 0; nt < 4; nt++) {
            int col = colw + nt * 8 + 2 * t;
            int c0 = col < N ? col : N - 1;        // acc==0 for OOB cols
            int c1 = col + 1 < N ? col + 1 : N - 1;
            asv[nt][0] = atts[c0]; asv[nt][1] = atts[c1];
            adv[nt][0] = attd[c0]; adv[nt][1] = attd[c1];
        }
#pragma unroll
        for (int mt = 0; mt < 4; mt++) {
            float s0 = 0.f, s1 = 0.f, d0 = 0.f, d1 = 0.f;
#pragma unroll
            for (int nt = 0; nt < 4; nt++) {
                s0 += acc[mt][nt][0] * asv[nt][0] + acc[mt][nt][1] * asv[nt][1];
                s1 += acc[mt][nt][2] * asv[nt][0] + acc[mt][nt][3] * asv[nt][1];
                d0 += acc[mt][nt][0] * adv[nt][0] + acc[mt][nt][1] * adv[nt][1];
                d1 += acc[mt][nt][2] * adv[nt][0] + acc[mt][nt][3] * adv[nt][1];
            }
            s0 += __shfl_xor_sync(0xFFFFFFFFu, s0, 1);
            s0 += __shfl_xor_sync(0xFFFFFFFFu, s0, 2);
            s1 += __shfl_xor_sync(0xFFFFFFFFu, s1, 1);
            s1 += __shfl_xor_sync(0xFFFFFFFFu, s1, 2);
            d0 += __shfl_xor_sync(0xFFFFFFFFu, d0, 1);
            d0 += __shfl_xor_sync(0xFFFFFFFFu, d0, 2);
            d1 += __shfl_xor_sync(0xFFFFFFFFu, d1, 1);
            d1 += __shfl_xor_sync(0xFFFFFFFFu, d1, 2);
            if (t == 0) {
                int row0 = bm + warpM * 64 + mt * 16 + g;
                if (row0 < M) {
                    atomicAdd(&g_as[row0 * H + hd], s0);
                    atomicAdd(&g_ad[row0 * H + hd], d0);
                }
                if (row0 + 8 < M) {
                    atomicAdd(&g_as[(row0 + 8) * H + hd], s1);
                    atomicAdd(&g_ad[(row0 + 8) * H + hd], d1);
                }
            }
        }
    }
}

// ---------------- zero a_s/a_d before each layer's GEMM ---------------------
__global__ void zero_asad(int n) {
    int i = blockIdx.x * blockDim.x + threadIdx.x;
    if (i < n) { g_as[i] = 0.f; g_ad[i] = 0.f; }
}

// ---------------- CSR build --------------------------------------------------
__global__ void k_zero_deg() {
    int i = blockIdx.x * blockDim.x + threadIdx.x;
    if (i < NN) g_deg[i] = 0;
}

__global__ void k_count(const int* __restrict__ ei) {
    int e = blockIdx.x * blockDim.x + threadIdx.x;
    if (e >= ETOT) return;
    int d = e < EE ? ei[EE + e] : e - EE;
    atomicAdd(&g_deg[d], 1);
}

__global__ __launch_bounds__(1024) void k_scan() {
    __shared__ int part[1024];
    const int SEG = (NN + 1023) / 1024;
    int t = threadIdx.x;
    int lo = t * SEG, hi = min(NN, lo + SEG);
    int s = 0;
    for (int i = lo; i < hi; i++) s += g_deg[i];
    part[t] = s;
    __syncthreads();
    for (int off = 1; off < 1024; off <<= 1) {
        int v = 0;
        if (t >= off) v = part[t - off];
        __syncthreads();
        if (t >= off) part[t] += v;
        __syncthreads();
    }
    int run = t ? part[t - 1] : 0;
    for (int i = lo; i < hi; i++) {
        g_off[i] = run;
        g_cur[i] = run;
        run += g_deg[i];
    }
    if (t == 0) g_off[NN] = part[1023];
}

__global__ void k_scatter(const int* __restrict__ ei) {
    int e = blockIdx.x * blockDim.x + threadIdx.x;
    if (e >= ETOT) return;
    int s, d;
    if (e < EE) { s = ei[e]; d = ei[EE + e]; }
    else        { s = d = e - EE; }
    int pos = atomicAdd(&g_cur[d], 1);
    g_srcs[pos] = s;
}

// ---------------- softmax coefs (H=4): one warp per dst node -----------------
__global__ __launch_bounds__(256) void attn_coef4() {
    int node = (blockIdx.x * blockDim.x + threadIdx.x) >> 5;
    int lane = threadIdx.x & 31;
    if (node >= NN) return;
    int beg = g_off[node];
    int deg = g_off[node + 1] - beg;

    float4 adv = *(const float4*)&g_ad[node * 4];
    float mx0 = -1e30f, mx1 = -1e30f, mx2 = -1e30f, mx3 = -1e30f;

    float c0 = 0.f, c1 = 0.f, c2 = 0.f, c3 = 0.f;
    bool have = lane < deg;
    if (have) {
        int s = g_srcs[beg + lane];
        float4 av = *(const float4*)&g_as[s * 4];
        c0 = av.x + adv.x; c1 = av.y + adv.y;
        c2 = av.z + adv.z; c3 = av.w + adv.w;
        c0 = c0 > 0.f ? c0 : 0.2f * c0;
        c1 = c1 > 0.f ? c1 : 0.2f * c1;
        c2 = c2 > 0.f ? c2 : 0.2f * c2;
        c3 = c3 > 0.f ? c3 : 0.2f * c3;
        mx0 = c0; mx1 = c1; mx2 = c2; mx3 = c3;
    }
    for (int base = 32; base < deg; base += 32) {
        int i = base + lane;
        if (i < deg) {
            int s = g_srcs[beg + i];
            float4 av = *(const float4*)&g_as[s * 4];
            float v0 = av.x + adv.x, v1 = av.y + adv.y;
            float v2 = av.z + adv.z, v3 = av.w + adv.w;
            v0 = v0 > 0.f ? v0 : 0.2f * v0;
            v1 = v1 > 0.f ? v1 : 0.2f * v1;
            v2 = v2 > 0.f ? v2 : 0.2f * v2;
            v3 = v3 > 0.f ? v3 : 0.2f * v3;
            mx0 = fmaxf(mx0, v0); mx1 = fmaxf(mx1, v1);
            mx2 = fmaxf(mx2, v2); mx3 = fmaxf(mx3, v3);
        }
    }
#pragma unroll
    for (int o = 16; o; o >>= 1) {
        mx0 = fmaxf(mx0, __shfl_xor_sync(0xFFFFFFFFu, mx0, o));
        mx1 = fmaxf(mx1, __shfl_xor_sync(0xFFFFFFFFu, mx1, o));
        mx2 = fmaxf(mx2, __shfl_xor_sync(0xFFFFFFFFu, mx2, o));
        mx3 = fmaxf(mx3, __shfl_xor_sync(0xFFFFFFFFu, mx3, o));
    }
    float s0 = 0.f, s1 = 0.f, s2 = 0.f, s3 = 0.f;
    if (have) {
        float a0 = __expf(c0 - mx0), a1 = __expf(c1 - mx1);
        float a2 = __expf(c2 - mx2), a3 = __expf(c3 - mx3);
        *(float4*)&g_e[(size_t)(beg + lane) * 4] = make_float4(a0, a1, a2, a3);
        s0 = a0; s1 = a1; s2 = a2; s3 = a3;
    }
    for (int base = 32; base < deg; base += 32) {
        int i = base + lane;
        if (i < deg) {
            int s = g_srcs[beg + i];
            float4 av = *(const float4*)&g_as[s * 4];
            float v0 = av.x + adv.x, v1 = av.y + adv.y;
            float v2 = av.z + adv.z, v3 = av.w + adv.w;
            v0 = v0 > 0.f ? v0 : 0.2f * v0;
            v1 = v1 > 0.f ? v1 : 0.2f * v1;
            v2 = v2 > 0.f ? v2 : 0.2f * v2;
            v3 = v3 > 0.f ? v3 : 0.2f * v3;
            float a0 = __expf(v0 - mx0), a1 = __expf(v1 - mx1);
            float a2 = __expf(v2 - mx2), a3 = __expf(v3 - mx3);
            *(float4*)&g_e[(size_t)(beg + i) * 4] = make_float4(a0, a1, a2, a3);
            s0 += a0; s1 += a1; s2 += a2; s3 += a3;
        }
    }
#pragma unroll
    for (int o = 16; o; o >>= 1) {
        s0 += __shfl_xor_sync(0xFFFFFFFFu, s0, o);
        s1 += __shfl_xor_sync(0xFFFFFFFFu, s1, o);
        s2 += __shfl_xor_sync(0xFFFFFFFFu, s2, o);
        s3 += __shfl_xor_sync(0xFFFFFFFFu, s3, o);
    }
    if (lane == 0)
        *(float4*)&g_r[node * 4] = make_float4(1.f / s0, 1.f / s1, 1.f / s2, 1.f / s3);
}

// ---------------- softmax coefs (H=1) ----------------------------------------
__global__ __launch_bounds__(256) void attn_coef1() {
    int node = (blockIdx.x * blockDim.x + threadIdx.x) >> 5;
    int lane = threadIdx.x & 31;
    if (node >= NN) return;
    int beg = g_off[node];
    int deg = g_off[node + 1] - beg;

    float adv = g_ad[node];
    float vc = 0.f;
    bool have = lane < deg;
    float mx = -1e30f;
    if (have) {
        int s = g_srcs[beg + lane];
        float v = g_as[s] + adv;
        vc = v > 0.f ? v : 0.2f * v;
        mx = vc;
    }
    for (int base = 32; base < deg; base += 32) {
        int i = base + lane;
        if (i < deg) {
            int s = g_srcs[beg + i];
            float v = g_as[s] + adv;
            v = v > 0.f ? v : 0.2f * v;
            mx = fmaxf(mx, v);
        }
    }
#pragma unroll
    for (int o = 16; o; o >>= 1) mx = fmaxf(mx, __shfl_xor_sync(0xFFFFFFFFu, mx, o));
    float sm = 0.f;
    if (have) {
        float a = __expf(vc - mx);
        g_e[beg + lane] = a;
        sm = a;
    }
    for (int base = 32; base < deg; base += 32) {
        int i = base + lane;
        if (i < deg) {
            int s = g_srcs[beg + i];
            float v = g_as[s] + adv;
            v = v > 0.f ? v : 0.2f * v;
            float a = __expf(v - mx);
            g_e[beg + i] = a;
            sm += a;
        }
    }
#pragma unroll
    for (int o = 16; o; o >>= 1) sm += __shfl_xor_sync(0xFFFFFFFFu, sm, o);
    if (lane == 0) g_r[node] = 1.f / sm;
}

// ---------------- aggregation: one warp per dst node, 256 channels ----------
__global__ __launch_bounds__(256) void aggr256(const float* __restrict__ h,
                                               const float* __restrict__ bias,
                                               float* __restrict__ obuf,
                                               int apply_elu) {
    int node = (blockIdx.x * blockDim.x + threadIdx.x) >> 5;
    int lane = threadIdx.x & 31;
    if (node >= NN) return;
    int beg = g_off[node];
    int deg = g_off[node + 1] - beg;
    int c  = lane * 8;
    int hd = lane >> 3;

    float4 a0 = make_float4(0.f, 0.f, 0.f, 0.f);
    float4 a1 = make_float4(0.f, 0.f, 0.f, 0.f);

    int i = 0;
    for (; i + 2 <= deg; i += 2) {      // 2 edges in flight (MLP)
        int s0 = g_srcs[beg + i];
        int s1 = g_srcs[beg + i + 1];
        float4 cf0 = *(const float4*)&g_e[(size_t)(beg + i) * 4];
        float4 cf1 = *(const float4*)&g_e[(size_t)(beg + i + 1) * 4];
        float k0 = hd == 0 ? cf0.x : hd == 1 ? cf0.y : hd == 2 ? cf0.z : cf0.w;
        float k1 = hd == 0 ? cf1.x : hd == 1 ? cf1.y : hd == 2 ? cf1.z : cf1.w;
        const float4* h0 = (const float4*)(h + (size_t)s0 * 256 + c);
        const float4* h1 = (const float4*)(h + (size_t)s1 * 256 + c);
        float4 u0 = h0[0], u1 = h0[1];
        float4 w0 = h1[0], w1 = h1[1];
        a0.x += k0 * u0.x; a0.y += k0 * u0.y; a0.z += k0 * u0.z; a0.w += k0 * u0.w;
        a1.x += k0 * u1.x; a1.y += k0 * u1.y; a1.z += k0 * u1.z; a1.w += k0 * u1.w;
        a0.x += k1 * w0.x; a0.y += k1 * w0.y; a0.z += k1 * w0.z; a0.w += k1 * w0.w;
        a1.x += k1 * w1.x; a1.y += k1 * w1.y; a1.z += k1 * w1.z; a1.w += k1 * w1.w;
    }
    if (i < deg) {
        int s0 = g_srcs[beg + i];
        float4 cf0 = *(const float4*)&g_e[(size_t)(beg + i) * 4];
        float k0 = hd == 0 ? cf0.x : hd == 1 ? cf0.y : hd == 2 ? cf0.z : cf0.w;
        const float4* h0 = (const float4*)(h + (size_t)s0 * 256 + c);
        float4 u0 = h0[0], u1 = h0[1];
        a0.x += k0 * u0.x; a0.y += k0 * u0.y; a0.z += k0 * u0.z; a0.w += k0 * u0.w;
        a1.x += k0 * u1.x; a1.y += k0 * u1.y; a1.z += k0 * u1.z; a1.w += k0 * u1.w;
    }
    float4 rv = *(const float4*)&g_r[node * 4];
    float r = hd == 0 ? rv.x : hd == 1 ? rv.y : hd == 2 ? rv.z : rv.w;
    float4 b0 = *(const float4*)&bias[c];
    float4 b1 = *(const float4*)&bias[c + 4];
    a0.x = a0.x * r + b0.x; a0.y = a0.y * r + b0.y;
    a0.z = a0.z * r + b0.z; a0.w = a0.w * r + b0.w;
    a1.x = a1.x * r + b1.x; a1.y = a1.y * r + b1.y;
    a1.z = a1.z * r + b1.z; a1.w = a1.w * r + b1.w;
    if (apply_elu) {
        a0.x = a0.x > 0.f ? a0.x : expm1f(a0.x);
        a0.y = a0.y > 0.f ? a0.y : expm1f(a0.y);
        a0.z = a0.z > 0.f ? a0.z : expm1f(a0.z);
        a0.w = a0.w > 0.f ? a0.w : expm1f(a0.w);
        a1.x = a1.x > 0.f ? a1.x : expm1f(a1.x);
        a1.y = a1.y > 0.f ? a1.y : expm1f(a1.y);
        a1.z = a1.z > 0.f ? a1.z : expm1f(a1.z);
        a1.w = a1.w > 0.f ? a1.w : expm1f(a1.w);
    }
    float4* op = (float4*)(obuf + (size_t)node * 256 + c);
    op[0] = a0;
    op[1] = a1;
}

// ---------------- aggregation, layer 3: 40 channels, H=1 ---------------------
__global__ __launch_bounds__(256) void aggr40(const float* __restrict__ h,
                                              const float* __restrict__ bias,
                                              float* __restrict__ out) {
    int node = (blockIdx.x * blockDim.x + threadIdx.x) >> 5;
    int lane = threadIdx.x & 31;
    if (node >= NN) return;
    int beg = g_off[node];
    int deg = g_off[node + 1] - beg;

    float4 acc = make_float4(0.f, 0.f, 0.f, 0.f);
    int c = lane * 4;
    bool act = lane < 10;

    int sp = g_srcs[beg];
    for (int i = 0; i < deg; i++) {
        int cs = sp;
        if (i + 1 < deg) sp = g_srcs[beg + i + 1];
        float coef = g_e[beg + i];
        if (act) {
            float4 v = *(const float4*)(h + (size_t)cs * 40 + c);
            acc.x += coef * v.x; acc.y += coef * v.y;
            acc.z += coef * v.z; acc.w += coef * v.w;
        }
    }
    if (act) {
        float r = g_r[node];
        float4 b = *(const float4*)&bias[c];
        acc.x = acc.x * r + b.x; acc.y = acc.y * r + b.y;
        acc.z = acc.z * r + b.z; acc.w = acc.w * r + b.w;
        *(float4*)(out + (size_t)node * 40 + c) = acc;
    }
}

// ---------------- driver ----------------------------------------------------
extern "C" void kernel_launch(void* const* d_in, const int* in_sizes, int n_in,
                              void* d_out, int out_size) {
    const float* x   = (const float*)d_in[0];
    const int*   ei  = (const int*)  d_in[1];
    const float* W1  = (const float*)d_in[2];
    const float* as1 = (const float*)d_in[3];
    const float* ad1 = (const float*)d_in[4];
    const float* b1  = (const float*)d_in[5];
    const float* W2  = (const float*)d_in[6];
    const float* as2 = (const float*)d_in[7];
    const float* ad2 = (const float*)d_in[8];
    const float* b2  = (const float*)d_in[9];
    const float* W3  = (const float*)d_in[10];
    const float* as3 = (const float*)d_in[11];
    const float* ad3 = (const float*)d_in[12];
    const float* b3  = (const float*)d_in[13];
    float* out = (float*)d_out;

    float *h, *buf;
    cudaGetSymbolAddress((void**)&h,   g_h);
    cudaGetSymbolAddress((void**)&buf, g_buf);

    const int TB = 256;
    int gE = (ETOT + TB - 1) / TB;
    int gW = (NN * 32 + TB - 1) / TB;   // one warp per node

    // ---- CSR by dst (edge structure shared by all layers) ----
    k_zero_deg<<<(NN + TB - 1) / TB, TB>>>();
    k_count  <<<gE, TB>>>(ei);
    k_scan   <<<1, 1024>>>();
    k_scatter<<<gE, TB>>>(ei);

    // ---- layer 1 ----
    dim3 g1((NN + 127) / 128, (D1 + 127) / 128);
    zero_asad <<<(NN * HEADS + TB - 1) / TB, TB>>>(NN * HEADS);
    gemm_tf32 <<<g1, TB>>>(x, W1, h, NN, D1, FIN, as1, ad1, HEADS, HID);
    attn_coef4<<<gW, TB>>>();
    aggr256   <<<gW, TB>>>(h, b1, buf, 1);

    // ---- layer 2 ----
    zero_asad <<<(NN * HEADS + TB - 1) / TB, TB>>>(NN * HEADS);
    gemm_tf32 <<<g1, TB>>>(buf, W2, h, NN, D1, D1, as2, ad2, HEADS, HID);
    attn_coef4<<<gW, TB>>>();
    aggr256   <<<gW, TB>>>(h, b2, buf, 1);

    // ---- layer 3 ----
    dim3 g3((NN + 127) / 128, 1);
    zero_asad <<<(NN + TB - 1) / TB, TB>>>(NN);
    gemm_tf32 <<<g3, TB>>>(buf, W3, h, NN, NCLS, D1, as3, ad3, 1, NCLS);
    attn_coef1<<<gW, TB>>>();
    aggr40    <<<gW, TB>>>(h, b3, out);
}

// round 9
// speedup vs baseline: 1.1549x; 1.0737x over previous
#include <cuda_runtime.h>
#include <math.h>

#define NN    50000
#define FIN   512
#define HEADS 4
#define HID   64
#define NCLS  40
#define EE    800000
#define ETOT  (EE + NN)      // 850000 (with self loops)
#define D1    (HEADS * HID)  // 256

// ---------------- scratch (device globals; no allocation allowed) ----------
static __device__ float g_h  [(size_t)NN * D1];      // GEMM output h
static __device__ float g_buf[(size_t)NN * D1];      // aggregated output / next input
static __device__ float g_as [NN * HEADS];
static __device__ float g_ad [NN * HEADS];
static __device__ int   g_deg[NN];
static __device__ int   g_off[NN + 1];
static __device__ int   g_cur[NN];
static __device__ int   g_srcs[ETOT];                // src node ids grouped by dst

// ---------------- tf32 helpers ---------------------------------------------
__device__ __forceinline__ unsigned f2tf(float f) {
    unsigned u;
    asm("cvt.rna.tf32.f32 %0, %1;" : "=r"(u) : "f"(f));
    return u;
}
__device__ __forceinline__ void tf_split(float f, unsigned& hi, unsigned& lo) {
    hi = f2tf(f);
    float r = f - __uint_as_float(hi);
    lo = f2tf(r);
}
__device__ __forceinline__ void mma_tf32(float c[4],
                                         unsigned a0, unsigned a1, unsigned a2, unsigned a3,
                                         unsigned b0, unsigned b1) {
    asm volatile(
        "mma.sync.aligned.m16n8k8.row.col.f32.tf32.tf32.f32 "
        "{%0,%1,%2,%3}, {%4,%5,%6,%7}, {%8,%9}, {%0,%1,%2,%3};"
        : "+f"(c[0]), "+f"(c[1]), "+f"(c[2]), "+f"(c[3])
        : "r"(a0), "r"(a1), "r"(a2), "r"(a3), "r"(b0), "r"(b1));
}

__device__ __forceinline__ void cp16(unsigned dst, const void* src, int srcsize) {
    asm volatile("cp.async.cg.shared.global [%0], [%1], 16, %2;"
                 :: "r"(dst), "l"(src), "r"(srcsize));
}

// ---------------- GEMM: C[M,N] = A[M,K] @ W[K,N], 3xTF32 tensor cores ------
// (exact R6 structure: cp.async 2-stage double buffer, in-loop tf32 split)
#define BK  16
#define SAK 20    // A smem k-stride (16 + 4 pad)
#define SB  136   // B smem n-stride
__global__ __launch_bounds__(256) void gemm_tf32(const float* __restrict__ A,
                                                 const float* __restrict__ W,
                                                 float* __restrict__ C,
                                                 int M, int N, int K) {
    __shared__ __align__(16) float As[2][128][SAK];
    __shared__ __align__(16) float Bs[2][BK][SB];

    int tid  = threadIdx.x;
    int lane = tid & 31;
    int wid  = tid >> 5;
    int warpM = wid & 1;
    int warpN = wid >> 1;
    int g = lane >> 2, t = lane & 3;

    int bm = blockIdx.x * 128;
    int bn = blockIdx.y * 128;

    float acc[4][4][4];
#pragma unroll
    for (int i = 0; i < 4; i++)
#pragma unroll
        for (int j = 0; j < 4; j++)
#pragma unroll
            for (int q = 0; q < 4; q++) acc[i][j][q] = 0.f;

    int ar = tid >> 1;
    int ak = (tid & 1) * 8;
    int bkr = tid >> 4;
    int bc  = (tid & 15) * 8;
    int arow = bm + ar; if (arow >= M) arow = M - 1;
    int bs0 = (bn + bc + 3 < N) ? 16 : 0;
    int bs1 = (bn + bc + 7 < N) ? 16 : 0;
    const float* aptr = A + (size_t)arow * K + ak;
    const float* bptr = W + (size_t)bkr * N + bn + bc;

    unsigned sA = (unsigned)__cvta_generic_to_shared(&As[0][0][0]);
    unsigned sB = (unsigned)__cvta_generic_to_shared(&Bs[0][0][0]);
    unsigned dA = sA + (ar * SAK + ak) * 4;
    unsigned dB = sB + (bkr * SB + bc) * 4;
    const unsigned stA = 128 * SAK * 4;
    const unsigned stB = BK * SB * 4;

    int T = K / BK;
    cp16(dA,      aptr,     16);
    cp16(dA + 16, aptr + 4, 16);
    cp16(dB,      bptr,     bs0);
    cp16(dB + 16, bptr + 4, bs1);
    asm volatile("cp.async.commit_group;");

    int rowb = warpM * 64 + g;
    int colb = warpN * 32 + g;

    for (int tt = 0; tt < T; tt++) {
        int cur = tt & 1;
        if (tt + 1 < T) {
            int nxt = cur ^ 1;
            const float* ap = aptr + (tt + 1) * BK;
            const float* bp = bptr + (size_t)(tt + 1) * BK * N;
            cp16(dA + nxt * stA,      ap,     16);
            cp16(dA + nxt * stA + 16, ap + 4, 16);
            cp16(dB + nxt * stB,      bp,     bs0);
            cp16(dB + nxt * stB + 16, bp + 4, bs1);
            asm volatile("cp.async.commit_group;");
            asm volatile("cp.async.wait_group 1;");
        } else {
            asm volatile("cp.async.commit_group;");
            asm volatile("cp.async.wait_group 0;");
        }
        __syncthreads();

        const float* Af = &As[cur][0][0];
        const float* Bf = &Bs[cur][0][0];
#pragma unroll
        for (int kk = 0; kk < BK; kk += 8) {
            unsigned aHi[4][4], aLo[4][4], bHi[4][2], bLo[4][2];
#pragma unroll
            for (int mt = 0; mt < 4; mt++) {
                int r = rowb + mt * 16;
                tf_split(Af[(r    ) * SAK + kk + t    ], aHi[mt][0], aLo[mt][0]);
                tf_split(Af[(r + 8) * SAK + kk + t    ], aHi[mt][1], aLo[mt][1]);
                tf_split(Af[(r    ) * SAK + kk + t + 4], aHi[mt][2], aLo[mt][2]);
                tf_split(Af[(r + 8) * SAK + kk + t + 4], aHi[mt][3], aLo[mt][3]);
            }
#pragma unroll
            for (int nt = 0; nt < 4; nt++) {
                int c = colb + nt * 8;
                tf_split(Bf[(kk + t    ) * SB + c], bHi[nt][0], bLo[nt][0]);
                tf_split(Bf[(kk + t + 4) * SB + c], bHi[nt][1], bLo[nt][1]);
            }
#pragma unroll
            for (int mt = 0; mt < 4; mt++)
#pragma unroll
                for (int nt = 0; nt < 4; nt++) {
                    mma_tf32(acc[mt][nt], aHi[mt][0], aHi[mt][1], aHi[mt][2], aHi[mt][3],
                             bLo[nt][0], bLo[nt][1]);
                    mma_tf32(acc[mt][nt], aLo[mt][0], aLo[mt][1], aLo[mt][2], aLo[mt][3],
                             bHi[nt][0], bHi[nt][1]);
                    mma_tf32(acc[mt][nt], aHi[mt][0], aHi[mt][1], aHi[mt][2], aHi[mt][3],
                             bHi[nt][0], bHi[nt][1]);
                }
        }
        __syncthreads();
    }

#pragma unroll
    for (int mt = 0; mt < 4; mt++) {
        int row0 = bm + warpM * 64 + mt * 16 + g;
#pragma unroll
        for (int nt = 0; nt < 4; nt++) {
            int col = bn + warpN * 32 + nt * 8 + 2 * t;
            if (col < N) {
                if (row0 < M)
                    *(float2*)&C[(size_t)row0 * N + col] =
                        make_float2(acc[mt][nt][0], acc[mt][nt][1]);
                if (row0 + 8 < M)
                    *(float2*)&C[(size_t)(row0 + 8) * N + col] =
                        make_float2(acc[mt][nt][2], acc[mt][nt][3]);
            }
        }
    }
}

// ---------------- CSR build --------------------------------------------------
__global__ void k_zero_deg() {
    int i = blockIdx.x * blockDim.x + threadIdx.x;
    if (i < NN) g_deg[i] = 0;
}

__global__ void k_count(const int* __restrict__ ei) {
    int e = blockIdx.x * blockDim.x + threadIdx.x;
    if (e >= ETOT) return;
    int d = e < EE ? ei[EE + e] : e - EE;
    atomicAdd(&g_deg[d], 1);
}

__global__ __launch_bounds__(1024) void k_scan() {
    __shared__ int part[1024];
    const int SEG = (NN + 1023) / 1024;
    int t = threadIdx.x;
    int lo = t * SEG, hi = min(NN, lo + SEG);
    int s = 0;
    for (int i = lo; i < hi; i++) s += g_deg[i];
    part[t] = s;
    __syncthreads();
    for (int off = 1; off < 1024; off <<= 1) {
        int v = 0;
        if (t >= off) v = part[t - off];
        __syncthreads();
        if (t >= off) part[t] += v;
        __syncthreads();
    }
    int run = t ? part[t - 1] : 0;
    for (int i = lo; i < hi; i++) {
        g_off[i] = run;
        g_cur[i] = run;
        run += g_deg[i];
    }
    if (t == 0) g_off[NN] = part[1023];
}

__global__ void k_scatter(const int* __restrict__ ei) {
    int e = blockIdx.x * blockDim.x + threadIdx.x;
    if (e >= ETOT) return;
    int s, d;
    if (e < EE) { s = ei[e]; d = ei[EE + e]; }
    else        { s = d = e - EE; }
    int pos = atomicAdd(&g_cur[d], 1);
    g_srcs[pos] = s;
}

// ---------------- per-node: a_s, a_d -----------------------------------------
__global__ void node_prep(const float* __restrict__ h,
                          const float* __restrict__ atts,
                          const float* __restrict__ attd,
                          int H, int C) {
    int warp = (blockIdx.x * blockDim.x + threadIdx.x) >> 5;
    int lane = threadIdx.x & 31;
    if (warp >= NN) return;
    int HC = H * C;
    const float* hr = h + (size_t)warp * HC;
    for (int hd = 0; hd < H; hd++) {
        float s = 0.f, d = 0.f;
        for (int c = lane; c < C; c += 32) {
            float v = hr[hd * C + c];
            s += v * atts[hd * C + c];
            d += v * attd[hd * C + c];
        }
#pragma unroll
        for (int o = 16; o; o >>= 1) {
            s += __shfl_down_sync(0xFFFFFFFFu, s, o);
            d += __shfl_down_sync(0xFFFFFFFFu, d, o);
        }
        if (lane == 0) {
            g_as[warp * H + hd] = s;
            g_ad[warp * H + hd] = d;
        }
    }
}

// ---------------- fused softmax + aggregation (H=4, 256 ch) -----------------
// One warp per dst node. Pass 1: per-head max (register-caches first 32 edges).
// Pass 2: exps -> per-warp smem, aggregation (unroll 2) with denominator
// accumulated in-loop (every lane sees every coef); normalize in epilogue.
__global__ __launch_bounds__(256) void aggr_fused4(const float* __restrict__ h,
                                                   const float* __restrict__ bias,
                                                   float* __restrict__ obuf,
                                                   int apply_elu) {
    __shared__ float4 earr[8][32];
    __shared__ int    sarr[8][32];
    int wrp  = threadIdx.x >> 5;
    int node = (blockIdx.x * blockDim.x + threadIdx.x) >> 5;
    int lane = threadIdx.x & 31;
    if (node >= NN) return;
    int beg = g_off[node];
    int deg = g_off[node + 1] - beg;

    float4 adv = *(const float4*)&g_ad[node * 4];

    // ---- pass 1: per-head max; cache first-block logits + srcs ----
    float c0 = 0.f, c1 = 0.f, c2 = 0.f, c3 = 0.f;
    int   sv = 0;
    float mx0 = -1e30f, mx1 = -1e30f, mx2 = -1e30f, mx3 = -1e30f;
    if (lane < deg) {
        sv = g_srcs[beg + lane];
        float4 av = *(const float4*)&g_as[sv * 4];
        c0 = av.x + adv.x; c1 = av.y + adv.y;
        c2 = av.z + adv.z; c3 = av.w + adv.w;
        c0 = c0 > 0.f ? c0 : 0.2f * c0;
        c1 = c1 > 0.f ? c1 : 0.2f * c1;
        c2 = c2 > 0.f ? c2 : 0.2f * c2;
        c3 = c3 > 0.f ? c3 : 0.2f * c3;
        mx0 = c0; mx1 = c1; mx2 = c2; mx3 = c3;
    }
    for (int base = 32; base < deg; base += 32) {
        int i = base + lane;
        if (i < deg) {
            int s = g_srcs[beg + i];
            float4 av = *(const float4*)&g_as[s * 4];
            float v0 = av.x + adv.x, v1 = av.y + adv.y;
            float v2 = av.z + adv.z, v3 = av.w + adv.w;
            v0 = v0 > 0.f ? v0 : 0.2f * v0;
            v1 = v1 > 0.f ? v1 : 0.2f * v1;
            v2 = v2 > 0.f ? v2 : 0.2f * v2;
            v3 = v3 > 0.f ? v3 : 0.2f * v3;
            mx0 = fmaxf(mx0, v0); mx1 = fmaxf(mx1, v1);
            mx2 = fmaxf(mx2, v2); mx3 = fmaxf(mx3, v3);
        }
    }
#pragma unroll
    for (int o = 16; o; o >>= 1) {
        mx0 = fmaxf(mx0, __shfl_xor_sync(0xFFFFFFFFu, mx0, o));
        mx1 = fmaxf(mx1, __shfl_xor_sync(0xFFFFFFFFu, mx1, o));
        mx2 = fmaxf(mx2, __shfl_xor_sync(0xFFFFFFFFu, mx2, o));
        mx3 = fmaxf(mx3, __shfl_xor_sync(0xFFFFFFFFu, mx3, o));
    }

    // ---- pass 2: exp -> smem, aggregate + denominator ----
    int c8 = lane * 8, hd = lane >> 3;
    float4 a0 = make_float4(0.f, 0.f, 0.f, 0.f);
    float4 a1 = make_float4(0.f, 0.f, 0.f, 0.f);
    float ssum = 0.f;

    for (int base = 0; base < deg; base += 32) {
        int len = min(32, deg - base);
        if (lane < len) {
            float v0, v1, v2, v3; int s;
            if (base == 0) { v0 = c0; v1 = c1; v2 = c2; v3 = c3; s = sv; }
            else {
                s = g_srcs[beg + base + lane];
                float4 av = *(const float4*)&g_as[s * 4];
                v0 = av.x + adv.x; v1 = av.y + adv.y;
                v2 = av.z + adv.z; v3 = av.w + adv.w;
                v0 = v0 > 0.f ? v0 : 0.2f * v0;
                v1 = v1 > 0.f ? v1 : 0.2f * v1;
                v2 = v2 > 0.f ? v2 : 0.2f * v2;
                v3 = v3 > 0.f ? v3 : 0.2f * v3;
            }
            earr[wrp][lane] = make_float4(__expf(v0 - mx0), __expf(v1 - mx1),
                                          __expf(v2 - mx2), __expf(v3 - mx3));
            sarr[wrp][lane] = s;
        }
        __syncwarp();
        int i = 0;
        for (; i + 2 <= len; i += 2) {
            float4 cfA = earr[wrp][i];
            float4 cfB = earr[wrp][i + 1];
            int sA = sarr[wrp][i];
            int sB = sarr[wrp][i + 1];
            float kA = hd == 0 ? cfA.x : hd == 1 ? cfA.y : hd == 2 ? cfA.z : cfA.w;
            float kB = hd == 0 ? cfB.x : hd == 1 ? cfB.y : hd == 2 ? cfB.z : cfB.w;
            const float4* hA = (const float4*)(h + (size_t)sA * 256 + c8);
            const float4* hB = (const float4*)(h + (size_t)sB * 256 + c8);
            float4 uA0 = hA[0], uA1 = hA[1];
            float4 uB0 = hB[0], uB1 = hB[1];
            a0.x += kA * uA0.x; a0.y += kA * uA0.y; a0.z += kA * uA0.z; a0.w += kA * uA0.w;
            a1.x += kA * uA1.x; a1.y += kA * uA1.y; a1.z += kA * uA1.z; a1.w += kA * uA1.w;
            a0.x += kB * uB0.x; a0.y += kB * uB0.y; a0.z += kB * uB0.z; a0.w += kB * uB0.w;
            a1.x += kB * uB1.x; a1.y += kB * uB1.y; a1.z += kB * uB1.z; a1.w += kB * uB1.w;
            ssum += kA + kB;
        }
        if (i < len) {
            float4 cfA = earr[wrp][i];
            int sA = sarr[wrp][i];
            float kA = hd == 0 ? cfA.x : hd == 1 ? cfA.y : hd == 2 ? cfA.z : cfA.w;
            const float4* hA = (const float4*)(h + (size_t)sA * 256 + c8);
            float4 uA0 = hA[0], uA1 = hA[1];
            a0.x += kA * uA0.x; a0.y += kA * uA0.y; a0.z += kA * uA0.z; a0.w += kA * uA0.w;
            a1.x += kA * uA1.x; a1.y += kA * uA1.y; a1.z += kA * uA1.z; a1.w += kA * uA1.w;
            ssum += kA;
        }
        __syncwarp();   // protect smem before next block overwrites
    }

    float r = 1.f / ssum;
    float4 b0 = *(const float4*)&bias[c8];
    float4 b1 = *(const float4*)&bias[c8 + 4];
    a0.x = a0.x * r + b0.x; a0.y = a0.y * r + b0.y;
    a0.z = a0.z * r + b0.z; a0.w = a0.w * r + b0.w;
    a1.x = a1.x * r + b1.x; a1.y = a1.y * r + b1.y;
    a1.z = a1.z * r + b1.z; a1.w = a1.w * r + b1.w;
    if (apply_elu) {
        a0.x = a0.x > 0.f ? a0.x : expm1f(a0.x);
        a0.y = a0.y > 0.f ? a0.y : expm1f(a0.y);
        a0.z = a0.z > 0.f ? a0.z : expm1f(a0.z);
        a0.w = a0.w > 0.f ? a0.w : expm1f(a0.w);
        a1.x = a1.x > 0.f ? a1.x : expm1f(a1.x);
        a1.y = a1.y > 0.f ? a1.y : expm1f(a1.y);
        a1.z = a1.z > 0.f ? a1.z : expm1f(a1.z);
        a1.w = a1.w > 0.f ? a1.w : expm1f(a1.w);
    }
    float4* op = (float4*)(obuf + (size_t)node * 256 + c8);
    op[0] = a0;
    op[1] = a1;
}

// ---------------- fused softmax + aggregation (H=1, 40 ch) -------------------
__global__ __launch_bounds__(256) void aggr_fused40(const float* __restrict__ h,
                                                    const float* __restrict__ bias,
                                                    float* __restrict__ out) {
    __shared__ float earr[8][32];
    __shared__ int   sarr[8][32];
    int wrp  = threadIdx.x >> 5;
    int node = (blockIdx.x * blockDim.x + threadIdx.x) >> 5;
    int lane = threadIdx.x & 31;
    if (node >= NN) return;
    int beg = g_off[node];
    int deg = g_off[node + 1] - beg;

    float adv = g_ad[node];

    // pass 1: max; cache first block
    float vc = 0.f;
    int   sv = 0;
    float mx = -1e30f;
    if (lane < deg) {
        sv = g_srcs[beg + lane];
        float v = g_as[sv] + adv;
        vc = v > 0.f ? v : 0.2f * v;
        mx = vc;
    }
    for (int base = 32; base < deg; base += 32) {
        int i = base + lane;
        if (i < deg) {
            int s = g_srcs[beg + i];
            float v = g_as[s] + adv;
            v = v > 0.f ? v : 0.2f * v;
            mx = fmaxf(mx, v);
        }
    }
#pragma unroll
    for (int o = 16; o; o >>= 1) mx = fmaxf(mx, __shfl_xor_sync(0xFFFFFFFFu, mx, o));

    // pass 2: exp -> smem, aggregate + denominator
    float4 acc = make_float4(0.f, 0.f, 0.f, 0.f);
    int c4 = lane * 4;
    bool act = lane < 10;
    float ssum = 0.f;

    for (int base = 0; base < deg; base += 32) {
        int len = min(32, deg - base);
        if (lane < len) {
            float v; int s;
            if (base == 0) { v = vc; s = sv; }
            else {
                s = g_srcs[beg + base + lane];
                float w = g_as[s] + adv;
                v = w > 0.f ? w : 0.2f * w;
            }
            earr[wrp][lane] = __expf(v - mx);
            sarr[wrp][lane] = s;
        }
        __syncwarp();
        for (int i = 0; i < len; i++) {
            float k = earr[wrp][i];
            int  ss = sarr[wrp][i];
            ssum += k;
            if (act) {
                float4 v = *(const float4*)(h + (size_t)ss * 40 + c4);
                acc.x += k * v.x; acc.y += k * v.y;
                acc.z += k * v.z; acc.w += k * v.w;
            }
        }
        __syncwarp();
    }
    if (act) {
        float r = 1.f / ssum;
        float4 b = *(const float4*)&bias[c4];
        acc.x = acc.x * r + b.x; acc.y = acc.y * r + b.y;
        acc.z = acc.z * r + b.z; acc.w = acc.w * r + b.w;
        *(float4*)(out + (size_t)node * 40 + c4) = acc;
    }
}

// ---------------- driver ----------------------------------------------------
extern "C" void kernel_launch(void* const* d_in, const int* in_sizes, int n_in,
                              void* d_out, int out_size) {
    const float* x   = (const float*)d_in[0];
    const int*   ei  = (const int*)  d_in[1];
    const float* W1  = (const float*)d_in[2];
    const float* as1 = (const float*)d_in[3];
    const float* ad1 = (const float*)d_in[4];
    const float* b1  = (const float*)d_in[5];
    const float* W2  = (const float*)d_in[6];
    const float* as2 = (const float*)d_in[7];
    const float* ad2 = (const float*)d_in[8];
    const float* b2  = (const float*)d_in[9];
    const float* W3  = (const float*)d_in[10];
    const float* as3 = (const float*)d_in[11];
    const float* ad3 = (const float*)d_in[12];
    const float* b3  = (const float*)d_in[13];
    float* out = (float*)d_out;

    float *h, *buf;
    cudaGetSymbolAddress((void**)&h,   g_h);
    cudaGetSymbolAddress((void**)&buf, g_buf);

    const int TB = 256;
    int gE = (ETOT + TB - 1) / TB;
    int gW = (NN * 32 + TB - 1) / TB;   // one warp per node

    // ---- CSR by dst (edge structure shared by all layers) ----
    k_zero_deg<<<(NN + TB - 1) / TB, TB>>>();
    k_count  <<<gE, TB>>>(ei);
    k_scan   <<<1, 1024>>>();
    k_scatter<<<gE, TB>>>(ei);

    // ---- layer 1 ----
    dim3 g1((NN + 127) / 128, (D1 + 127) / 128);
    gemm_tf32  <<<g1, TB>>>(x, W1, h, NN, D1, FIN);
    node_prep  <<<gW, TB>>>(h, as1, ad1, HEADS, HID);
    aggr_fused4<<<gW, TB>>>(h, b1, buf, 1);

    // ---- layer 2 ----
    gemm_tf32  <<<g1, TB>>>(buf, W2, h, NN, D1, D1);
    node_prep  <<<gW, TB>>>(h, as2, ad2, HEADS, HID);
    aggr_fused4<<<gW, TB>>>(h, b2, buf, 1);

    // ---- layer 3 ----
    dim3 g3((NN + 127) / 128, 1);
    gemm_tf32   <<<g3, TB>>>(buf, W3, h, NN, NCLS, D1);
    node_prep   <<<gW, TB>>>(h, as3, ad3, 1, NCLS);
    aggr_fused40<<<gW, TB>>>(h, b3, out);
}